// round 2
// baseline (speedup 1.0000x reference)
#include <cuda_runtime.h>
#include <math.h>

#define NB 32
#define NS 2048
#define NH 1024
#define NU 1024

// scratch (no cudaMalloc allowed)
__device__ float g_c[NB * NU];       // b1 + b2 + query@W2
__device__ float g_score[NB * NS];   // pre-softmax scores

// ---------------------------------------------------------------------------
// Kernel 1: c[b,u] = query[b]@W2[:,u] + b1[u] + b2[u]
// grid (32, 4), block 256
// ---------------------------------------------------------------------------
__global__ void __launch_bounds__(256) k_bias(const float* __restrict__ query,
                                              const float* __restrict__ W2,
                                              const float* __restrict__ b1,
                                              const float* __restrict__ b2) {
    int b = blockIdx.x;
    int u = blockIdx.y * 256 + threadIdx.x;
    __shared__ float qs[NH];
    for (int i = threadIdx.x; i < NH; i += 256) qs[i] = query[b * NH + i];
    __syncthreads();
    float a0 = 0.f, a1 = 0.f, a2 = 0.f, a3 = 0.f;
    #pragma unroll 4
    for (int h = 0; h < NH; h += 4) {
        a0 = fmaf(qs[h + 0], W2[(h + 0) * NU + u], a0);
        a1 = fmaf(qs[h + 1], W2[(h + 1) * NU + u], a1);
        a2 = fmaf(qs[h + 2], W2[(h + 2) * NU + u], a2);
        a3 = fmaf(qs[h + 3], W2[(h + 3) * NU + u], a3);
    }
    g_c[b * NU + u] = ((a0 + a1) + (a2 + a3)) + b1[u] + b2[u];
}

// ---------------------------------------------------------------------------
// Kernel 2: fused GEMM + tanh + dot(V) -> score
//   rows = flattened (b,s) in [0, 65536); each CTA handles 128 rows (one b),
//   loops the full U dimension in 8 tiles of 128, K in 32 steps of 32.
//   Microtile 8x8 per thread (256 threads = 16x16).
// grid 512, block 256
// ---------------------------------------------------------------------------
__global__ void __launch_bounds__(256) k_score(const float* __restrict__ values,
                                               const float* __restrict__ W1,
                                               const float* __restrict__ Vv) {
    __shared__ float As[32][128];   // [k][m]
    __shared__ float Bs[32][128];   // [k][n]
    __shared__ float cs[NU];
    __shared__ float vs[NU];
    __shared__ float red[16][128];

    const int tid = threadIdx.x;
    const int tx = tid & 15;        // col group
    const int ty = tid >> 4;        // row group
    const int row0 = blockIdx.x * 128;
    const int b = row0 / NS;        // 2048 % 128 == 0 -> single batch per CTA

    for (int i = tid; i < NU; i += 256) {
        cs[i] = g_c[b * NU + i];
        vs[i] = Vv[i];
    }

    float rowsum[8];
    #pragma unroll
    for (int i = 0; i < 8; i++) rowsum[i] = 0.f;

    const int la_m = tid >> 3;          // 0..31
    const int la_k = (tid & 7) * 4;     // 0,4,...,28
    const int lb_k = tid >> 5;          // 0..7
    const int lb_n = (tid & 31) * 4;    // 0..124

    for (int nt = 0; nt < 8; nt++) {
        float acc[8][8];
        #pragma unroll
        for (int i = 0; i < 8; i++)
            #pragma unroll
            for (int j = 0; j < 8; j++) acc[i][j] = 0.f;

        for (int kt = 0; kt < 32; kt++) {
            __syncthreads();  // protect smem from previous iteration's readers
            #pragma unroll
            for (int p = 0; p < 4; p++) {
                int m = la_m + p * 32;
                float4 v = *(const float4*)&values[(size_t)(row0 + m) * NH + kt * 32 + la_k];
                As[la_k + 0][m] = v.x;
                As[la_k + 1][m] = v.y;
                As[la_k + 2][m] = v.z;
                As[la_k + 3][m] = v.w;
            }
            #pragma unroll
            for (int p = 0; p < 4; p++) {
                int k = lb_k + p * 8;
                *(float4*)&Bs[k][lb_n] =
                    *(const float4*)&W1[(size_t)(kt * 32 + k) * NU + nt * 128 + lb_n];
            }
            __syncthreads();

            #pragma unroll
            for (int k = 0; k < 32; k++) {
                float4 va0 = *(const float4*)&As[k][ty * 8];
                float4 va1 = *(const float4*)&As[k][ty * 8 + 4];
                float a[8] = {va0.x, va0.y, va0.z, va0.w, va1.x, va1.y, va1.z, va1.w};
                float bb[8];
                #pragma unroll
                for (int j = 0; j < 8; j++) bb[j] = Bs[k][tx + 16 * j];
                #pragma unroll
                for (int i = 0; i < 8; i++)
                    #pragma unroll
                    for (int j = 0; j < 8; j++)
                        acc[i][j] = fmaf(a[i], bb[j], acc[i][j]);
            }
        }

        // epilogue for this N-tile: tanh(acc + c) * V, reduce over n into rowsum
        #pragma unroll
        for (int j = 0; j < 8; j++) {
            int n = nt * 128 + tx + 16 * j;
            float cv = cs[n], vv = vs[n];
            #pragma unroll
            for (int i = 0; i < 8; i++)
                rowsum[i] += tanhf(acc[i][j] + cv) * vv;
        }
    }

    // cross-thread (tx) reduction per row
    #pragma unroll
    for (int i = 0; i < 8; i++) red[tx][ty * 8 + i] = rowsum[i];
    __syncthreads();
    if (tid < 128) {
        float s = 0.f;
        #pragma unroll
        for (int x = 0; x < 16; x++) s += red[x][tid];
        g_score[row0 + tid] = s;   // bv omitted: softmax-invariant
    }
}

// ---------------------------------------------------------------------------
// Kernel 3: softmax over S per batch, writes attention weights to d_out region
// grid 32, block 256
// ---------------------------------------------------------------------------
__global__ void __launch_bounds__(256) k_softmax(float* __restrict__ wout) {
    int b = blockIdx.x, t = threadIdx.x;
    __shared__ float sh[256];
    float mx = -3.4e38f;
    for (int s = t; s < NS; s += 256) mx = fmaxf(mx, g_score[b * NS + s]);
    sh[t] = mx;
    __syncthreads();
    for (int o = 128; o > 0; o >>= 1) {
        if (t < o) sh[t] = fmaxf(sh[t], sh[t + o]);
        __syncthreads();
    }
    mx = sh[0];
    __syncthreads();
    float sum = 0.f;
    for (int s = t; s < NS; s += 256) {
        float e = expf(g_score[b * NS + s] - mx);
        wout[b * NS + s] = e;
        sum += e;
    }
    sh[t] = sum;
    __syncthreads();
    for (int o = 128; o > 0; o >>= 1) {
        if (t < o) sh[t] += sh[t + o];
        __syncthreads();
    }
    float inv = 1.f / sh[0];
    for (int s = t; s < NS; s += 256) wout[b * NS + s] *= inv;
}

// ---------------------------------------------------------------------------
// Kernel 4: context[b,h] = sum_s w[b,s] * values[b,s,h]
// grid (32, 8), block 128
// ---------------------------------------------------------------------------
__global__ void __launch_bounds__(128) k_context(const float* __restrict__ values,
                                                 const float* __restrict__ w,
                                                 float* __restrict__ ctx) {
    int b = blockIdx.x;
    int h = blockIdx.y * 128 + threadIdx.x;
    __shared__ float ws[NS];
    for (int s = threadIdx.x; s < NS; s += 128) ws[s] = w[b * NS + s];
    __syncthreads();
    const float* vp = values + (size_t)b * NS * NH + h;
    float a0 = 0.f, a1 = 0.f, a2 = 0.f, a3 = 0.f;
    #pragma unroll 2
    for (int s = 0; s < NS; s += 4) {
        a0 = fmaf(ws[s + 0], vp[(size_t)(s + 0) * NH], a0);
        a1 = fmaf(ws[s + 1], vp[(size_t)(s + 1) * NH], a1);
        a2 = fmaf(ws[s + 2], vp[(size_t)(s + 2) * NH], a2);
        a3 = fmaf(ws[s + 3], vp[(size_t)(s + 3) * NH], a3);
    }
    ctx[b * NH + h] = (a0 + a1) + (a2 + a3);
}

// ---------------------------------------------------------------------------
extern "C" void kernel_launch(void* const* d_in, const int* in_sizes, int n_in,
                              void* d_out, int out_size) {
    const float* query  = (const float*)d_in[0];   // [32,1024]
    const float* values = (const float*)d_in[1];   // [32,2048,1024]
    const float* W1     = (const float*)d_in[2];   // [1024,1024]
    const float* b1     = (const float*)d_in[3];   // [1024]
    const float* W2     = (const float*)d_in[4];   // [1024,1024]
    const float* b2     = (const float*)d_in[5];   // [1024]
    const float* V      = (const float*)d_in[6];   // [1024,1]
    // d_in[7] = bv : softmax-invariant, unused.

    float* out = (float*)d_out;
    float* ctx = out;              // context_vector  [32,1024]
    float* wts = out + NB * NH;    // attention_weights [32,2048,1]

    dim3 gb(NB, 4);
    k_bias<<<gb, 256>>>(query, W2, b1, b2);
    k_score<<<(NB * NS) / 128, 256>>>(values, W1, V);
    k_softmax<<<NB, 256>>>(wts);
    dim3 gc(NB, 8);
    k_context<<<gc, 128>>>(values, wts, ctx);
}

// round 3
// speedup vs baseline: 1.0007x; 1.0007x over previous
#include <cuda_runtime.h>
#include <math.h>

#define NB 32
#define NS 2048
#define NH 1024
#define NU 1024

// scratch (no cudaMalloc allowed)
__device__ float g_c[NB * NU];       // b1 + b2 + query@W2
__device__ float g_score[NB * NS];   // pre-softmax scores

// ---------------------------------------------------------------------------
// Kernel 1: c[b,u] = query[b]@W2[:,u] + b1[u] + b2[u]
// grid (32, 4), block 256
// ---------------------------------------------------------------------------
__global__ void __launch_bounds__(256) k_bias(const float* __restrict__ query,
                                              const float* __restrict__ W2,
                                              const float* __restrict__ b1,
                                              const float* __restrict__ b2) {
    int b = blockIdx.x;
    int u = blockIdx.y * 256 + threadIdx.x;
    __shared__ float qs[NH];
    for (int i = threadIdx.x; i < NH; i += 256) qs[i] = query[b * NH + i];
    __syncthreads();
    float a0 = 0.f, a1 = 0.f, a2 = 0.f, a3 = 0.f;
    #pragma unroll 4
    for (int h = 0; h < NH; h += 4) {
        a0 = fmaf(qs[h + 0], W2[(h + 0) * NU + u], a0);
        a1 = fmaf(qs[h + 1], W2[(h + 1) * NU + u], a1);
        a2 = fmaf(qs[h + 2], W2[(h + 2) * NU + u], a2);
        a3 = fmaf(qs[h + 3], W2[(h + 3) * NU + u], a3);
    }
    g_c[b * NU + u] = ((a0 + a1) + (a2 + a3)) + b1[u] + b2[u];
}

// ---------------------------------------------------------------------------
// Kernel 2: fused GEMM + tanh + dot(V) -> score
//   rows = flattened (b,s) in [0, 65536); each CTA handles 128 rows (one b),
//   loops the full U dimension in 8 tiles of 128, K in 32 steps of 32.
//   Microtile 8x8 per thread (256 threads = 16x16).
// grid 512, block 256
// ---------------------------------------------------------------------------
__global__ void __launch_bounds__(256) k_score(const float* __restrict__ values,
                                               const float* __restrict__ W1,
                                               const float* __restrict__ Vv) {
    __shared__ float As[32][128];   // [k][m]
    __shared__ float Bs[32][128];   // [k][n]
    __shared__ float cs[NU];
    __shared__ float vs[NU];
    __shared__ float red[16][128];

    const int tid = threadIdx.x;
    const int tx = tid & 15;        // col group
    const int ty = tid >> 4;        // row group
    const int row0 = blockIdx.x * 128;
    const int b = row0 / NS;        // 2048 % 128 == 0 -> single batch per CTA

    for (int i = tid; i < NU; i += 256) {
        cs[i] = g_c[b * NU + i];
        vs[i] = Vv[i];
    }

    float rowsum[8];
    #pragma unroll
    for (int i = 0; i < 8; i++) rowsum[i] = 0.f;

    const int la_m = tid >> 3;          // 0..31
    const int la_k = (tid & 7) * 4;     // 0,4,...,28
    const int lb_k = tid >> 5;          // 0..7
    const int lb_n = (tid & 31) * 4;    // 0..124

    for (int nt = 0; nt < 8; nt++) {
        float acc[8][8];
        #pragma unroll
        for (int i = 0; i < 8; i++)
            #pragma unroll
            for (int j = 0; j < 8; j++) acc[i][j] = 0.f;

        for (int kt = 0; kt < 32; kt++) {
            __syncthreads();  // protect smem from previous iteration's readers
            #pragma unroll
            for (int p = 0; p < 4; p++) {
                int m = la_m + p * 32;
                float4 v = *(const float4*)&values[(size_t)(row0 + m) * NH + kt * 32 + la_k];
                As[la_k + 0][m] = v.x;
                As[la_k + 1][m] = v.y;
                As[la_k + 2][m] = v.z;
                As[la_k + 3][m] = v.w;
            }
            #pragma unroll
            for (int p = 0; p < 4; p++) {
                int k = lb_k + p * 8;
                *(float4*)&Bs[k][lb_n] =
                    *(const float4*)&W1[(size_t)(kt * 32 + k) * NU + nt * 128 + lb_n];
            }
            __syncthreads();

            #pragma unroll
            for (int k = 0; k < 32; k++) {
                float4 va0 = *(const float4*)&As[k][ty * 8];
                float4 va1 = *(const float4*)&As[k][ty * 8 + 4];
                float a[8] = {va0.x, va0.y, va0.z, va0.w, va1.x, va1.y, va1.z, va1.w};
                float bb[8];
                #pragma unroll
                for (int j = 0; j < 8; j++) bb[j] = Bs[k][tx + 16 * j];
                #pragma unroll
                for (int i = 0; i < 8; i++)
                    #pragma unroll
                    for (int j = 0; j < 8; j++)
                        acc[i][j] = fmaf(a[i], bb[j], acc[i][j]);
            }
        }

        // epilogue for this N-tile: tanh(acc + c) * V, reduce over n into rowsum
        #pragma unroll
        for (int j = 0; j < 8; j++) {
            int n = nt * 128 + tx + 16 * j;
            float cv = cs[n], vv = vs[n];
            #pragma unroll
            for (int i = 0; i < 8; i++)
                rowsum[i] += tanhf(acc[i][j] + cv) * vv;
        }
    }

    // cross-thread (tx) reduction per row
    #pragma unroll
    for (int i = 0; i < 8; i++) red[tx][ty * 8 + i] = rowsum[i];
    __syncthreads();
    if (tid < 128) {
        float s = 0.f;
        #pragma unroll
        for (int x = 0; x < 16; x++) s += red[x][tid];
        g_score[row0 + tid] = s;   // bv omitted: softmax-invariant
    }
}

// ---------------------------------------------------------------------------
// Kernel 3: softmax over S per batch, writes attention weights to d_out region
// grid 32, block 256
// ---------------------------------------------------------------------------
__global__ void __launch_bounds__(256) k_softmax(float* __restrict__ wout) {
    int b = blockIdx.x, t = threadIdx.x;
    __shared__ float sh[256];
    float mx = -3.4e38f;
    for (int s = t; s < NS; s += 256) mx = fmaxf(mx, g_score[b * NS + s]);
    sh[t] = mx;
    __syncthreads();
    for (int o = 128; o > 0; o >>= 1) {
        if (t < o) sh[t] = fmaxf(sh[t], sh[t + o]);
        __syncthreads();
    }
    mx = sh[0];
    __syncthreads();
    float sum = 0.f;
    for (int s = t; s < NS; s += 256) {
        float e = expf(g_score[b * NS + s] - mx);
        wout[b * NS + s] = e;
        sum += e;
    }
    sh[t] = sum;
    __syncthreads();
    for (int o = 128; o > 0; o >>= 1) {
        if (t < o) sh[t] += sh[t + o];
        __syncthreads();
    }
    float inv = 1.f / sh[0];
    for (int s = t; s < NS; s += 256) wout[b * NS + s] *= inv;
}

// ---------------------------------------------------------------------------
// Kernel 4: context[b,h] = sum_s w[b,s] * values[b,s,h]
// grid (32, 8), block 128
// ---------------------------------------------------------------------------
__global__ void __launch_bounds__(128) k_context(const float* __restrict__ values,
                                                 const float* __restrict__ w,
                                                 float* __restrict__ ctx) {
    int b = blockIdx.x;
    int h = blockIdx.y * 128 + threadIdx.x;
    __shared__ float ws[NS];
    for (int s = threadIdx.x; s < NS; s += 128) ws[s] = w[b * NS + s];
    __syncthreads();
    const float* vp = values + (size_t)b * NS * NH + h;
    float a0 = 0.f, a1 = 0.f, a2 = 0.f, a3 = 0.f;
    #pragma unroll 2
    for (int s = 0; s < NS; s += 4) {
        a0 = fmaf(ws[s + 0], vp[(size_t)(s + 0) * NH], a0);
        a1 = fmaf(ws[s + 1], vp[(size_t)(s + 1) * NH], a1);
        a2 = fmaf(ws[s + 2], vp[(size_t)(s + 2) * NH], a2);
        a3 = fmaf(ws[s + 3], vp[(size_t)(s + 3) * NH], a3);
    }
    ctx[b * NH + h] = (a0 + a1) + (a2 + a3);
}

// ---------------------------------------------------------------------------
extern "C" void kernel_launch(void* const* d_in, const int* in_sizes, int n_in,
                              void* d_out, int out_size) {
    const float* query  = (const float*)d_in[0];   // [32,1024]
    const float* values = (const float*)d_in[1];   // [32,2048,1024]
    const float* W1     = (const float*)d_in[2];   // [1024,1024]
    const float* b1     = (const float*)d_in[3];   // [1024]
    const float* W2     = (const float*)d_in[4];   // [1024,1024]
    const float* b2     = (const float*)d_in[5];   // [1024]
    const float* V      = (const float*)d_in[6];   // [1024,1]
    // d_in[7] = bv : softmax-invariant, unused.

    float* out = (float*)d_out;
    float* ctx = out;              // context_vector  [32,1024]
    float* wts = out + NB * NH;    // attention_weights [32,2048,1]

    dim3 gb(NB, 4);
    k_bias<<<gb, 256>>>(query, W2, b1, b2);
    k_score<<<(NB * NS) / 128, 256>>>(values, W1, V);
    k_softmax<<<NB, 256>>>(wts);
    dim3 gc(NB, 8);
    k_context<<<gc, 128>>>(values, wts, ctx);
}

// round 4
// speedup vs baseline: 1.0010x; 1.0002x over previous
#include <cuda_runtime.h>
#include <math.h>

#define NB 32
#define NS 2048
#define NH 1024
#define NU 1024

// scratch (no cudaMalloc allowed)
__device__ float g_c[NB * NU];       // b1 + b2 + query@W2
__device__ float g_score[NB * NS];   // pre-softmax scores

// ---------------------------------------------------------------------------
// Kernel 1: c[b,u] = query[b]@W2[:,u] + b1[u] + b2[u]
// grid (32, 4), block 256
// ---------------------------------------------------------------------------
__global__ void __launch_bounds__(256) k_bias(const float* __restrict__ query,
                                              const float* __restrict__ W2,
                                              const float* __restrict__ b1,
                                              const float* __restrict__ b2) {
    int b = blockIdx.x;
    int u = blockIdx.y * 256 + threadIdx.x;
    __shared__ float qs[NH];
    for (int i = threadIdx.x; i < NH; i += 256) qs[i] = query[b * NH + i];
    __syncthreads();
    float a0 = 0.f, a1 = 0.f, a2 = 0.f, a3 = 0.f;
    #pragma unroll 4
    for (int h = 0; h < NH; h += 4) {
        a0 = fmaf(qs[h + 0], W2[(h + 0) * NU + u], a0);
        a1 = fmaf(qs[h + 1], W2[(h + 1) * NU + u], a1);
        a2 = fmaf(qs[h + 2], W2[(h + 2) * NU + u], a2);
        a3 = fmaf(qs[h + 3], W2[(h + 3) * NU + u], a3);
    }
    g_c[b * NU + u] = ((a0 + a1) + (a2 + a3)) + b1[u] + b2[u];
}

// ---------------------------------------------------------------------------
// Kernel 2: fused GEMM + tanh + dot(V) -> score
//   rows = flattened (b,s) in [0, 65536); each CTA handles 128 rows (one b),
//   loops the full U dimension in 8 tiles of 128, K in 32 steps of 32.
//   Microtile 8x8 per thread (256 threads = 16x16).
// grid 512, block 256
// ---------------------------------------------------------------------------
__global__ void __launch_bounds__(256) k_score(const float* __restrict__ values,
                                               const float* __restrict__ W1,
                                               const float* __restrict__ Vv) {
    __shared__ float As[32][128];   // [k][m]
    __shared__ float Bs[32][128];   // [k][n]
    __shared__ float cs[NU];
    __shared__ float vs[NU];
    __shared__ float red[16][128];

    const int tid = threadIdx.x;
    const int tx = tid & 15;        // col group
    const int ty = tid >> 4;        // row group
    const int row0 = blockIdx.x * 128;
    const int b = row0 / NS;        // 2048 % 128 == 0 -> single batch per CTA

    for (int i = tid; i < NU; i += 256) {
        cs[i] = g_c[b * NU + i];
        vs[i] = Vv[i];
    }

    float rowsum[8];
    #pragma unroll
    for (int i = 0; i < 8; i++) rowsum[i] = 0.f;

    const int la_m = tid >> 3;          // 0..31
    const int la_k = (tid & 7) * 4;     // 0,4,...,28
    const int lb_k = tid >> 5;          // 0..7
    const int lb_n = (tid & 31) * 4;    // 0..124

    for (int nt = 0; nt < 8; nt++) {
        float acc[8][8];
        #pragma unroll
        for (int i = 0; i < 8; i++)
            #pragma unroll
            for (int j = 0; j < 8; j++) acc[i][j] = 0.f;

        for (int kt = 0; kt < 32; kt++) {
            __syncthreads();  // protect smem from previous iteration's readers
            #pragma unroll
            for (int p = 0; p < 4; p++) {
                int m = la_m + p * 32;
                float4 v = *(const float4*)&values[(size_t)(row0 + m) * NH + kt * 32 + la_k];
                As[la_k + 0][m] = v.x;
                As[la_k + 1][m] = v.y;
                As[la_k + 2][m] = v.z;
                As[la_k + 3][m] = v.w;
            }
            #pragma unroll
            for (int p = 0; p < 4; p++) {
                int k = lb_k + p * 8;
                *(float4*)&Bs[k][lb_n] =
                    *(const float4*)&W1[(size_t)(kt * 32 + k) * NU + nt * 128 + lb_n];
            }
            __syncthreads();

            #pragma unroll
            for (int k = 0; k < 32; k++) {
                float4 va0 = *(const float4*)&As[k][ty * 8];
                float4 va1 = *(const float4*)&As[k][ty * 8 + 4];
                float a[8] = {va0.x, va0.y, va0.z, va0.w, va1.x, va1.y, va1.z, va1.w};
                float bb[8];
                #pragma unroll
                for (int j = 0; j < 8; j++) bb[j] = Bs[k][tx + 16 * j];
                #pragma unroll
                for (int i = 0; i < 8; i++)
                    #pragma unroll
                    for (int j = 0; j < 8; j++)
                        acc[i][j] = fmaf(a[i], bb[j], acc[i][j]);
            }
        }

        // epilogue for this N-tile: tanh(acc + c) * V, reduce over n into rowsum
        #pragma unroll
        for (int j = 0; j < 8; j++) {
            int n = nt * 128 + tx + 16 * j;
            float cv = cs[n], vv = vs[n];
            #pragma unroll
            for (int i = 0; i < 8; i++)
                rowsum[i] += tanhf(acc[i][j] + cv) * vv;
        }
    }

    // cross-thread (tx) reduction per row
    #pragma unroll
    for (int i = 0; i < 8; i++) red[tx][ty * 8 + i] = rowsum[i];
    __syncthreads();
    if (tid < 128) {
        float s = 0.f;
        #pragma unroll
        for (int x = 0; x < 16; x++) s += red[x][tid];
        g_score[row0 + tid] = s;   // bv omitted: softmax-invariant
    }
}

// ---------------------------------------------------------------------------
// Kernel 3: softmax over S per batch, writes attention weights to d_out region
// grid 32, block 256
// ---------------------------------------------------------------------------
__global__ void __launch_bounds__(256) k_softmax(float* __restrict__ wout) {
    int b = blockIdx.x, t = threadIdx.x;
    __shared__ float sh[256];
    float mx = -3.4e38f;
    for (int s = t; s < NS; s += 256) mx = fmaxf(mx, g_score[b * NS + s]);
    sh[t] = mx;
    __syncthreads();
    for (int o = 128; o > 0; o >>= 1) {
        if (t < o) sh[t] = fmaxf(sh[t], sh[t + o]);
        __syncthreads();
    }
    mx = sh[0];
    __syncthreads();
    float sum = 0.f;
    for (int s = t; s < NS; s += 256) {
        float e = expf(g_score[b * NS + s] - mx);
        wout[b * NS + s] = e;
        sum += e;
    }
    sh[t] = sum;
    __syncthreads();
    for (int o = 128; o > 0; o >>= 1) {
        if (t < o) sh[t] += sh[t + o];
        __syncthreads();
    }
    float inv = 1.f / sh[0];
    for (int s = t; s < NS; s += 256) wout[b * NS + s] *= inv;
}

// ---------------------------------------------------------------------------
// Kernel 4: context[b,h] = sum_s w[b,s] * values[b,s,h]
// grid (32, 8), block 128
// ---------------------------------------------------------------------------
__global__ void __launch_bounds__(128) k_context(const float* __restrict__ values,
                                                 const float* __restrict__ w,
                                                 float* __restrict__ ctx) {
    int b = blockIdx.x;
    int h = blockIdx.y * 128 + threadIdx.x;
    __shared__ float ws[NS];
    for (int s = threadIdx.x; s < NS; s += 128) ws[s] = w[b * NS + s];
    __syncthreads();
    const float* vp = values + (size_t)b * NS * NH + h;
    float a0 = 0.f, a1 = 0.f, a2 = 0.f, a3 = 0.f;
    #pragma unroll 2
    for (int s = 0; s < NS; s += 4) {
        a0 = fmaf(ws[s + 0], vp[(size_t)(s + 0) * NH], a0);
        a1 = fmaf(ws[s + 1], vp[(size_t)(s + 1) * NH], a1);
        a2 = fmaf(ws[s + 2], vp[(size_t)(s + 2) * NH], a2);
        a3 = fmaf(ws[s + 3], vp[(size_t)(s + 3) * NH], a3);
    }
    ctx[b * NH + h] = (a0 + a1) + (a2 + a3);
}

// ---------------------------------------------------------------------------
extern "C" void kernel_launch(void* const* d_in, const int* in_sizes, int n_in,
                              void* d_out, int out_size) {
    const float* query  = (const float*)d_in[0];   // [32,1024]
    const float* values = (const float*)d_in[1];   // [32,2048,1024]
    const float* W1     = (const float*)d_in[2];   // [1024,1024]
    const float* b1     = (const float*)d_in[3];   // [1024]
    const float* W2     = (const float*)d_in[4];   // [1024,1024]
    const float* b2     = (const float*)d_in[5];   // [1024]
    const float* V      = (const float*)d_in[6];   // [1024,1]
    // d_in[7] = bv : softmax-invariant, unused.

    float* out = (float*)d_out;
    float* ctx = out;              // context_vector  [32,1024]
    float* wts = out + NB * NH;    // attention_weights [32,2048,1]

    dim3 gb(NB, 4);
    k_bias<<<gb, 256>>>(query, W2, b1, b2);
    k_score<<<(NB * NS) / 128, 256>>>(values, W1, V);
    k_softmax<<<NB, 256>>>(wts);
    dim3 gc(NB, 8);
    k_context<<<gc, 128>>>(values, wts, ctx);
}